// round 1
// baseline (speedup 1.0000x reference)
#include <cuda_runtime.h>
#include <math.h>

// DotAttention: context[b,f] = sum_t softmax_t(<hd[b],he[b,t]>) * he[b,t,f]
// b=64, t=2048, f=1024, all fp32.
//
// Single-pass online softmax (flash style): each he row is read from HBM
// exactly once and used for both the score dot-product and the weighted
// accumulation. Split-T across CTAs with partial-softmax merge.

#define BATCH   64
#define TOK     2048
#define FDIM    1024
#define F4      (FDIM / 4)      // 256 float4 per row
#define SPLITS  8
#define TCHUNK  (TOK / SPLITS)  // 256 tokens per CTA
#define NWARP   8               // 256 threads

// Scratch (allocation-free: __device__ globals)
__device__ float4 g_part_ctx[BATCH * SPLITS * F4];  // 2 MB
__device__ float  g_part_m[BATCH * SPLITS];
__device__ float  g_part_l[BATCH * SPLITS];

__global__ __launch_bounds__(256, 2)
void dotattn_pass1(const float* __restrict__ hd, const float* __restrict__ he)
{
    const int b    = blockIdx.y;
    const int s    = blockIdx.x;
    const int tid  = threadIdx.x;
    const int lane = tid & 31;
    const int warp = tid >> 5;

    // Shared: decoder hidden (4 KB) + per-warp merge buffers (32 KB + eps)
    __shared__ float4 s_q[F4];
    __shared__ float4 s_acc[NWARP][F4];
    __shared__ float  s_m[NWARP], s_l[NWARP];

    // Stage q = hd[b,:] into smem (coalesced)
    {
        const float4* hd4 = (const float4*)(hd + (size_t)b * FDIM);
        if (tid < F4) s_q[tid] = hd4[tid];
    }
    __syncthreads();

    // Per-lane online-softmax state. Lane covers f4 indices j*32+lane, j=0..7
    // (i.e. f = (j*32+lane)*4 .. +3) -> warp loads are 512B contiguous.
    float  m = -INFINITY;
    float  l = 0.0f;
    float4 acc[8];
#pragma unroll
    for (int j = 0; j < 8; j++) acc[j] = make_float4(0.f, 0.f, 0.f, 0.f);

    const int t0 = s * TCHUNK;
    for (int t = t0 + warp; t < t0 + TCHUNK; t += NWARP) {
        const float4* he4 = (const float4*)(he + ((size_t)b * TOK + t) * FDIM);

        float4 v[8];
#pragma unroll
        for (int j = 0; j < 8; j++) v[j] = he4[j * 32 + lane];

        // partial dot over this lane's 32 elements
        float sc = 0.0f;
#pragma unroll
        for (int j = 0; j < 8; j++) {
            float4 q = s_q[j * 32 + lane];
            sc += v[j].x * q.x + v[j].y * q.y + v[j].z * q.z + v[j].w * q.w;
        }
        // warp reduce
#pragma unroll
        for (int o = 16; o > 0; o >>= 1)
            sc += __shfl_xor_sync(0xffffffffu, sc, o);

        // online softmax update
        const float nm   = fmaxf(m, sc);
        const float corr = __expf(m - nm);   // exp(-inf)=0 handles first iter
        const float w    = __expf(sc - nm);
        l = l * corr + w;
        m = nm;
#pragma unroll
        for (int j = 0; j < 8; j++) {
            acc[j].x = acc[j].x * corr + w * v[j].x;
            acc[j].y = acc[j].y * corr + w * v[j].y;
            acc[j].z = acc[j].z * corr + w * v[j].z;
            acc[j].w = acc[j].w * corr + w * v[j].w;
        }
    }

    // ---- merge the 8 warps of this CTA ----
#pragma unroll
    for (int j = 0; j < 8; j++) s_acc[warp][j * 32 + lane] = acc[j];
    if (lane == 0) { s_m[warp] = m; s_l[warp] = l; }
    __syncthreads();

    float M = s_m[0];
#pragma unroll
    for (int w2 = 1; w2 < NWARP; w2++) M = fmaxf(M, s_m[w2]);
    float e[NWARP];
    float L = 0.0f;
#pragma unroll
    for (int w2 = 0; w2 < NWARP; w2++) {
        e[w2] = __expf(s_m[w2] - M);
        L += s_l[w2] * e[w2];
    }

    // each thread owns one f4 index
    float4 c = make_float4(0.f, 0.f, 0.f, 0.f);
#pragma unroll
    for (int w2 = 0; w2 < NWARP; w2++) {
        float4 a = s_acc[w2][tid];
        c.x += a.x * e[w2];
        c.y += a.y * e[w2];
        c.z += a.z * e[w2];
        c.w += a.w * e[w2];
    }
    g_part_ctx[((size_t)b * SPLITS + s) * F4 + tid] = c;
    if (tid == 0) {
        g_part_m[b * SPLITS + s] = M;
        g_part_l[b * SPLITS + s] = L;
    }
}

__global__ __launch_bounds__(256)
void dotattn_pass2(float* __restrict__ out)
{
    const int b   = blockIdx.x;
    const int tid = threadIdx.x;

    float gm = -INFINITY;
#pragma unroll
    for (int s = 0; s < SPLITS; s++) gm = fmaxf(gm, g_part_m[b * SPLITS + s]);

    float e[SPLITS];
    float gl = 0.0f;
#pragma unroll
    for (int s = 0; s < SPLITS; s++) {
        e[s] = __expf(g_part_m[b * SPLITS + s] - gm);
        gl += g_part_l[b * SPLITS + s] * e[s];
    }
    const float inv = 1.0f / gl;

    float4 c = make_float4(0.f, 0.f, 0.f, 0.f);
#pragma unroll
    for (int s = 0; s < SPLITS; s++) {
        float4 a = g_part_ctx[((size_t)b * SPLITS + s) * F4 + tid];
        c.x += a.x * e[s];
        c.y += a.y * e[s];
        c.z += a.z * e[s];
        c.w += a.w * e[s];
    }
    c.x *= inv; c.y *= inv; c.z *= inv; c.w *= inv;
    ((float4*)out)[(size_t)b * F4 + tid] = c;
}

extern "C" void kernel_launch(void* const* d_in, const int* in_sizes, int n_in,
                              void* d_out, int out_size)
{
    const float* hd = (const float*)d_in[0];  // (64, 1024)
    const float* he = (const float*)d_in[1];  // (64, 2048, 1024)
    float* out = (float*)d_out;               // (64, 1024)

    dim3 grid1(SPLITS, BATCH);
    dotattn_pass1<<<grid1, 256>>>(hd, he);
    dotattn_pass2<<<BATCH, 256>>>(out);
}